// round 17
// baseline (speedup 1.0000x reference)
#include <cuda_runtime.h>
#include <cuda_bf16.h>
#include <math.h>
#include <stdint.h>

typedef __nv_bfloat16 bf16;

#define T_TOK 8192
#define D_DIM 1024
#define E_EXP 8
#define TOPK  2
#define FFD   2048
#define W1S   (FFD * E_EXP)
#define NPAIR (T_TOK * TOPK)
#define BM 128
#define NT_ROW 136
#define CAP (NT_ROW * BM)

// ---------------- static device scratch ----------------
// Referenced ONLY inside device code — never passed as kernel arguments
// (host shadow-symbol trap).
__device__ __align__(16) bf16  g_Whi[(size_t)E_EXP * FFD * D_DIM];
__device__ __align__(16) bf16  g_Wlo[(size_t)E_EXP * FFD * D_DIM];
__device__ __align__(16) bf16  g_Ahi[(size_t)CAP * D_DIM];
__device__ __align__(16) bf16  g_Alo[(size_t)CAP * D_DIM];
__device__ __align__(16) bf16  g_Hhi[(size_t)CAP * FFD];
__device__ __align__(16) bf16  g_Hlo[(size_t)CAP * FFD];
__device__ int   g_pair_token[CAP];
__device__ float g_slot_w[CAP];
__device__ int   g_sel[NPAIR];
__device__ float g_topw[NPAIR];
__device__ int   g_count[E_EXP];
__device__ int   g_cursor[E_EXP];
__device__ int   g_off[E_EXP + 1];
__device__ float g_z_acc;
__device__ float g_p_acc[E_EXP];

__device__ __forceinline__ float gelu_exact(float v) {
    return 0.5f * v * (1.0f + erff(v * 0.70710678118654752440f));
}
__device__ __forceinline__ uint32_t pack2(bf16 a, bf16 b) {
    return ((uint32_t)__bfloat16_as_ushort(b) << 16) | (uint32_t)__bfloat16_as_ushort(a);
}
__device__ __forceinline__ void split1(float f, bf16& h, bf16& l) {
    h = __float2bfloat16(f);
    l = __float2bfloat16(f - __bfloat162float(h));
}
__device__ __forceinline__ uint32_t smem_u32(const void* p) {
    uint32_t a;
    asm("{ .reg .u64 t; cvta.to.shared.u64 t, %1; cvt.u32.u64 %0, t; }" : "=r"(a) : "l"(p));
    return a;
}
__device__ __forceinline__ void cpa16(uint32_t dst, const void* src) {
    asm volatile("cp.async.cg.shared.global [%0], [%1], 16;" :: "r"(dst), "l"(src) : "memory");
}
__device__ __forceinline__ void cp_commit() {
    asm volatile("cp.async.commit_group;" ::: "memory");
}
template<int N>
__device__ __forceinline__ void cp_wait() {
    asm volatile("cp.async.wait_group %0;" :: "n"(N) : "memory");
}
__device__ __forceinline__ void ldsm4(uint32_t* r, uint32_t addr) {
    asm volatile("ldmatrix.sync.aligned.m8n8.x4.shared.b16 {%0,%1,%2,%3}, [%4];"
                 : "=r"(r[0]), "=r"(r[1]), "=r"(r[2]), "=r"(r[3]) : "r"(addr));
}
__device__ __forceinline__ void mma16816(float* d, const uint32_t* a, const uint32_t* b) {
    asm volatile("mma.sync.aligned.m16n8k16.row.col.f32.bf16.bf16.f32 "
                 "{%0,%1,%2,%3}, {%4,%5,%6,%7}, {%8,%9}, {%0,%1,%2,%3};"
                 : "+f"(d[0]), "+f"(d[1]), "+f"(d[2]), "+f"(d[3])
                 : "r"(a[0]), "r"(a[1]), "r"(a[2]), "r"(a[3]), "r"(b[0]), "r"(b[1]));
}
__device__ __forceinline__ void redadd(float* p, float v) {
    asm volatile("red.global.add.f32 [%0], %1;" :: "l"(p), "f"(v) : "memory");
}

// ---------------- init / zero ----------------
__global__ void k_init() {
    int i = blockIdx.x * 256 + threadIdx.x;
    if (i < CAP) g_pair_token[i] = -1;
    if (i < E_EXP) { g_count[i] = 0; g_cursor[i] = 0; g_p_acc[i] = 0.0f; }
    if (i == 0) g_z_acc = 0.0f;
}
__global__ void k_zero(float* __restrict__ out, int n) {
    int i = blockIdx.x * 256 + threadIdx.x;
    if (i < n) out[i] = 0.0f;
}

// ---------------- router ----------------
__global__ __launch_bounds__(256) void k_router(const float* __restrict__ x,
                                                const float* __restrict__ rw) {
    __shared__ float xs[D_DIM];
    __shared__ float logits[E_EXP];
    int t = blockIdx.x;
    const float* xr = x + (size_t)t * D_DIM;
    for (int i = threadIdx.x; i < D_DIM; i += 256) xs[i] = xr[i];
    __syncthreads();
    int w = threadIdx.x >> 5, lane = threadIdx.x & 31;
    float s = 0.0f;
    const float* we = rw + (size_t)w * D_DIM;
    for (int i = lane; i < D_DIM; i += 32) s += xs[i] * we[i];
    for (int o = 16; o; o >>= 1) s += __shfl_xor_sync(0xFFFFFFFFu, s, o);
    if (lane == 0) logits[w] = s;
    __syncthreads();
    if (threadIdx.x == 0) {
        float mx = logits[0];
        for (int e = 1; e < E_EXP; e++) mx = fmaxf(mx, logits[e]);
        float p[E_EXP]; float se = 0.0f;
        for (int e = 0; e < E_EXP; e++) { p[e] = expf(logits[e] - mx); se += p[e]; }
        float inv = 1.0f / se;
        for (int e = 0; e < E_EXP; e++) p[e] *= inv;
        float lse = mx + logf(se);
        atomicAdd(&g_z_acc, lse * lse);
        for (int e = 0; e < E_EXP; e++) atomicAdd(&g_p_acc[e], p[e]);
        int i0 = 0;
        for (int e = 1; e < E_EXP; e++) if (p[e] > p[i0]) i0 = e;
        int i1 = -1;
        for (int e = 0; e < E_EXP; e++) {
            if (e == i0) continue;
            if (i1 < 0 || p[e] > p[i1]) i1 = e;
        }
        float s2 = p[i0] + p[i1];
        g_sel[t * 2 + 0] = i0; g_sel[t * 2 + 1] = i1;
        g_topw[t * 2 + 0] = p[i0] / s2; g_topw[t * 2 + 1] = p[i1] / s2;
        atomicAdd(&g_count[i0], 1); atomicAdd(&g_count[i1], 1);
    }
}

__global__ void k_scan() {
    if (threadIdx.x == 0) {
        int off = 0;
        for (int e = 0; e < E_EXP; e++) {
            g_off[e] = off;
            off += ((g_count[e] + BM - 1) / BM) * BM;
        }
        g_off[E_EXP] = off;
    }
}

__global__ void k_scatter() {
    int t = blockIdx.x * 256 + threadIdx.x;
    if (t >= T_TOK) return;
    #pragma unroll
    for (int k = 0; k < TOPK; k++) {
        int e = g_sel[t * 2 + k];
        int pos = atomicAdd(&g_cursor[e], 1);
        int slot = g_off[e] + pos;
        g_pair_token[slot] = t;
        g_slot_w[slot] = g_topw[t * 2 + k];
    }
}

// ---------------- gather + split activations -> g_Ahi/g_Alo ----------------
__global__ __launch_bounds__(256) void k_gather(const float* __restrict__ x) {
    int s = blockIdx.x;
    int tok = g_pair_token[s];
    int i = threadIdx.x;
    float4 v = make_float4(0.f, 0.f, 0.f, 0.f);
    if (tok >= 0) v = ((const float4*)(x + (size_t)tok * D_DIM))[i];
    bf16 h0, h1, h2, h3, l0, l1, l2, l3;
    split1(v.x, h0, l0); split1(v.y, h1, l1); split1(v.z, h2, l2); split1(v.w, h3, l3);
    uint2 uh, ul;
    uh.x = pack2(h0, h1); uh.y = pack2(h2, h3);
    ul.x = pack2(l0, l1); ul.y = pack2(l2, l3);
    ((uint2*)(g_Ahi + (size_t)s * D_DIM))[i] = uh;
    ((uint2*)(g_Alo + (size_t)s * D_DIM))[i] = ul;
}

// ---------------- weight transpose+split -> g_Whi/g_Wlo ----------------
template<bool W1MODE>
__global__ __launch_bounds__(256) void k_tsplit(const float* __restrict__ src) {
    constexpr int R = W1MODE ? D_DIM : FFD;
    constexpr int C = W1MODE ? W1S : D_DIM;
    __shared__ float ts[32][33];
    size_t zoff = (size_t)blockIdx.z * R * C;
    int c0 = blockIdx.x * 32, r0 = blockIdx.y * 32;
    int tx = threadIdx.x & 31, ty = threadIdx.x >> 5;
    #pragma unroll
    for (int j = 0; j < 4; j++)
        ts[ty + j * 8][tx] = src[zoff + (size_t)(r0 + ty + j * 8) * C + c0 + tx];
    __syncthreads();
    #pragma unroll
    for (int j = 0; j < 4; j++) {
        float v = ts[tx][ty + j * 8];
        bf16 hh, ll;
        split1(v, hh, ll);
        size_t o = zoff + (size_t)(c0 + ty + j * 8) * R + r0 + tx;
        g_Whi[o] = hh; g_Wlo[o] = ll;
    }
}

// ---------------- tensor-core grouped GEMM ----------------
// CTA 128x128, BK=32, 8 warps (2x4), warp tile 64x32, PITCH 40 (80B rows).
// 3-stage cp.async circular pipeline, ONE __syncthreads per chunk.
#define PITCH 40
#define TILEB (128 * PITCH * 2)     /* 10240 B per operand tile */
#define STG   (4 * TILEB)           /* 40960 B per stage */
#define DSMEM (3 * STG)             /* 122880 B */

template<bool IS1>
__global__ __launch_bounds__(256) void k_gemm(float* __restrict__ outp) {
    constexpr int KTOT = IS1 ? D_DIM : FFD;
    constexpr int NBT  = IS1 ? FFD : D_DIM;
    constexpr int NKC  = KTOT / 32;
    extern __shared__ char dynsm[];
    const uint32_t sb = smem_u32(dynsm);
    __shared__ int   toks[128];
    __shared__ float ws[128];

    const int row0 = blockIdx.y * BM;
    if (row0 >= g_off[E_EXP]) return;
    int e = 0;
    while (row0 >= g_off[e + 1]) e++;
    const int nbase = blockIdx.x * 128;

    const int tid = threadIdx.x;
    const int wid = tid >> 5, lane = tid & 31;
    const int warp_m = wid & 1, warp_n = wid >> 1;

    if (!IS1 && tid < 128) {
        toks[tid] = g_pair_token[row0 + tid];
        ws[tid]   = g_slot_w[row0 + tid];
    }

    // ---- cp.async addressing: thread owns row lr, 16-elem half ----
    const int lr = tid >> 1, half = tid & 1;
    const bf16* pAh = (IS1 ? g_Ahi : g_Hhi) + (size_t)(row0 + lr) * KTOT + half * 16;
    const bf16* pAl = (IS1 ? g_Alo : g_Hlo) + (size_t)(row0 + lr) * KTOT + half * 16;
    const bf16* pBh = g_Whi + (size_t)(e * NBT + nbase + lr) * KTOT + half * 16;
    const bf16* pBl = g_Wlo + (size_t)(e * NBT + nbase + lr) * KTOT + half * 16;
    const uint32_t dOff = (uint32_t)(lr * 80 + half * 32);

    auto cp_stage = [&](int kc, int s) {
        uint32_t st = sb + s * STG + dOff;
        const bf16* a = pAh + kc * 32;
        const bf16* l = pAl + kc * 32;
        const bf16* b = pBh + kc * 32;
        const bf16* q = pBl + kc * 32;
        cpa16(st,                 a); cpa16(st + 16,             a + 8);
        cpa16(st + TILEB,         l); cpa16(st + TILEB + 16,     l + 8);
        cpa16(st + 2 * TILEB,     b); cpa16(st + 2 * TILEB + 16, b + 8);
        cpa16(st + 3 * TILEB,     q); cpa16(st + 3 * TILEB + 16, q + 8);
    };

    float acc[4][4][4];
    #pragma unroll
    for (int mt = 0; mt < 4; mt++)
        #pragma unroll
        for (int nt = 0; nt < 4; nt++)
            #pragma unroll
            for (int j = 0; j < 4; j++) acc[mt][nt][j] = 0.0f;

    const int g = lane >> 2, tg = lane & 3;

    // ---- ldmatrix per-thread addressing ----
    const int a_row = warp_m * 64 + (lane & 15);
    const int a_col = (lane >> 4) * 8;
    const int m8 = lane >> 3, r8 = lane & 7;
    const int b_row = warp_n * 32 + ((m8 >> 1) & 1) * 8 + r8;
    const int b_col = (m8 & 1) * 8;

    // ---- prologue: stages 0, 1 ----
    cp_stage(0, 0); cp_commit();
    cp_stage(1, 1); cp_commit();

    int s_cur = 0, s_nxt = 2;
    for (int kc = 0; kc < NKC; kc++) {
        cp_wait<1>();
        __syncthreads();
        if (kc + 2 < NKC) cp_stage(kc + 2, s_nxt);
        cp_commit();

        const uint32_t stA = sb + s_cur * STG;
        #pragma unroll
        for (int ks = 0; ks < 2; ks++) {
            const int cb = ks * 16;
            uint32_t aH[4][4], aL[4][4], bH[2][4], bL[2][4];
            #pragma unroll
            for (int mt = 0; mt < 4; mt++) {
                uint32_t off = (uint32_t)(((a_row + mt * 16) * PITCH + cb + a_col) * 2);
                ldsm4(aH[mt], stA + off);
                ldsm4(aL[mt], stA + TILEB + off);
            }
            #pragma unroll
            for (int p = 0; p < 2; p++) {
                uint32_t off = (uint32_t)(((b_row + p * 16) * PITCH + cb + b_col) * 2);
                ldsm4(bH[p], stA + 2 * TILEB + off);
                ldsm4(bL[p], stA + 3 * TILEB + off);
            }
            #pragma unroll
            for (int mt = 0; mt < 4; mt++)
                #pragma unroll
                for (int p = 0; p < 2; p++)
                    #pragma unroll
                    for (int sub = 0; sub < 2; sub++) {
                        float* d = acc[mt][p * 2 + sub];
                        mma16816(d, aH[mt], &bH[p][sub * 2]);
                        mma16816(d, aH[mt], &bL[p][sub * 2]);
                        mma16816(d, aL[mt], &bH[p][sub * 2]);
                    }
        }
        s_cur = (s_cur == 2) ? 0 : s_cur + 1;
        s_nxt = (s_nxt == 2) ? 0 : s_nxt + 1;
    }

    // ---- epilogue ----
    #pragma unroll
    for (int mt = 0; mt < 4; mt++) {
        const int rr = warp_m * 64 + mt * 16 + g;
        #pragma unroll
        for (int nt = 0; nt < 4; nt++) {
            const int c = nbase + warp_n * 32 + nt * 8 + tg * 2;
            float* d = acc[mt][nt];
            if constexpr (IS1) {
                const int r_lo = row0 + rr;
                float f0 = gelu_exact(d[0]), f1 = gelu_exact(d[1]);
                float f2 = gelu_exact(d[2]), f3 = gelu_exact(d[3]);
                bf16 h0, l0, h1, l1, h2, l2, h3, l3;
                split1(f0, h0, l0); split1(f1, h1, l1);
                split1(f2, h2, l2); split1(f3, h3, l3);
                *(uint32_t*)(g_Hhi + (size_t)r_lo * FFD + c)       = pack2(h0, h1);
                *(uint32_t*)(g_Hlo + (size_t)r_lo * FFD + c)       = pack2(l0, l1);
                *(uint32_t*)(g_Hhi + (size_t)(r_lo + 8) * FFD + c) = pack2(h2, h3);
                *(uint32_t*)(g_Hlo + (size_t)(r_lo + 8) * FFD + c) = pack2(l2, l3);
            } else {
                int t0 = toks[rr], t1 = toks[rr + 8];
                float w0 = ws[rr], w1 = ws[rr + 8];
                if (t0 >= 0) {
                    float* p = outp + (size_t)t0 * D_DIM + c;
                    redadd(p, w0 * d[0]); redadd(p + 1, w0 * d[1]);
                }
                if (t1 >= 0) {
                    float* p = outp + (size_t)t1 * D_DIM + c;
                    redadd(p, w1 * d[2]); redadd(p + 1, w1 * d[3]);
                }
            }
        }
    }
}

// ---------------- final scalars ----------------
__global__ void k_final(float* __restrict__ out, int out_size) {
    if (threadIdx.x == 0 && out_size >= T_TOK * D_DIM + 2) {
        float z = g_z_acc / (float)T_TOK;
        float lb = 0.0f;
        for (int e = 0; e < E_EXP; e++) {
            float f_i = (float)g_count[e] / (float)(T_TOK * TOPK);
            float p_i = g_p_acc[e] / (float)T_TOK;
            lb += f_i * p_i;
        }
        lb *= (float)E_EXP;
        out[T_TOK * D_DIM + 0] = z;
        out[T_TOK * D_DIM + 1] = lb;
    }
}

extern "C" void kernel_launch(void* const* d_in, const int* in_sizes, int n_in,
                              void* d_out, int out_size) {
    const float* x  = (const float*)d_in[0];
    const float* rw = (const float*)d_in[1];
    const float* w1 = (const float*)d_in[2];
    const float* w2 = (const float*)d_in[3];
    float* out = (float*)d_out;

    cudaFuncSetAttribute(k_gemm<true>,  cudaFuncAttributeMaxDynamicSharedMemorySize, DSMEM);
    cudaFuncSetAttribute(k_gemm<false>, cudaFuncAttributeMaxDynamicSharedMemorySize, DSMEM);

    const int nout = T_TOK * D_DIM + 2;
    k_zero<<<(nout + 255) / 256, 256>>>(out, out_size < nout ? out_size : nout);
    k_init<<<(CAP + 255) / 256, 256>>>();
    k_router<<<T_TOK, 256>>>(x, rw);
    k_scan<<<1, 32>>>();
    k_scatter<<<(T_TOK + 255) / 256, 256>>>();
    k_gather<<<CAP, 256>>>(x);
    // W1T: [D][E*FF] -> [e*FF+n][D]
    k_tsplit<true><<<dim3(W1S / 32, D_DIM / 32, 1), 256>>>(w1);
    k_gemm<true><<<dim3(FFD / 128, NT_ROW), 256, DSMEM>>>(out);
    // W2T: per-expert [FF][D] -> [e*D+n][FF]  (reuses the same buffer)
    k_tsplit<false><<<dim3(D_DIM / 32, FFD / 32, E_EXP), 256>>>(w2);
    k_gemm<false><<<dim3(D_DIM / 128, NT_ROW), 256, DSMEM>>>(out);
    k_final<<<1, 32>>>(out, out_size);
}